// round 11
// baseline (speedup 1.0000x reference)
#include <cuda_runtime.h>
#include <math.h>
#include <stdint.h>

#define BS    512
#define LNUM  68
#define IMG   224
#define RS    7
#define R2    49
#define LL    (LNUM * LNUM)     // 4624
#define NTHR  128               // 4 warps
#define NWARP 4
#define FULLM 0xFFFFFFFFu
#define NGRP  ((LL - 4) / 4)    // 1155 float4 store groups per batch

__device__ double   g_sumL = 0.0;
__device__ double   g_sumM = 0.0;
__device__ unsigned g_done = 0u;

__device__ __forceinline__ uint32_t smem_u32(const void* p) {
    return (uint32_t)__cvta_generic_to_shared(p);
}

// linspace(-3.5,3.5,7)[k] / 224 * 2 — identical op order to the reference.
__device__ __forceinline__ float xval(int k) {
    float x = -3.5f + (float)k * (7.0f / 6.0f);
    if (k == RS - 1) x = 3.5f;
    return x / 224.0f * 2.0f;
}

// One region sample; exact replica of the reference's grid_sample-nearest
// arithmetic (rintf == jnp.round, half-even).
__device__ __forceinline__ float sample(const float* __restrict__ dimg,
                                        float fx, float fy, float cx, float cy)
{
    float gy = fy + cy;
    float gx = fx + cx;
    float iy = ((gy + 1.0f) * 224.0f - 1.0f) * 0.5f;
    float ix = ((gx + 1.0f) * 224.0f - 1.0f) * 0.5f;
    int yi = (int)rintf(iy);
    int xi = (int)rintf(ix);
    bool v = (yi >= 0) & (yi < IMG) & (xi >= 0) & (xi < IMG);
    int yc = min(max(yi, 0), IMG - 1);
    int xc = min(max(xi, 0), IMG - 1);
    float val = __ldg(dimg + yc * IMG + xc);
    return v ? val : 0.0f;
}

__global__ __launch_bounds__(NTHR, 5) void fused_kernel(
    const float* __restrict__ rel,
    const float* __restrict__ depth,
    const float* __restrict__ lm,
    const float* __restrict__ sf,
    const float* __restrict__ bbox,
    float* __restrict__ out)
{
    __shared__ float  s_rel[LL];             // 18496 B, staged via cp.async.bulk
    __shared__ float  s_reg[LNUM * R2];      // 13328 B, stride 49 (odd -> no conflicts)
    __shared__ float  smed[LNUM];
    __shared__ float2 s_mm[LNUM];            // (med*500, mask)
    __shared__ float  s_mom;
    __shared__ int    s_cnt[3];
    __shared__ double redL[NWARP];
    __shared__ bool   s_last;
    __shared__ __align__(8) unsigned long long s_mbar;

    int b    = blockIdx.x;
    int tid  = threadIdx.x;
    int wid  = tid >> 5;
    int lane = tid & 31;

    const size_t base = (size_t)b * LL;
    const float* relb = rel + base;

    // ---- phase 0: bulk copy rel[batch] -> smem (overlaps gather+sort) ----
    uint32_t mb = smem_u32(&s_mbar);
    if (tid == 0) {
        asm volatile("mbarrier.init.shared.b64 [%0], 1;" :: "r"(mb) : "memory");
        asm volatile("fence.proxy.async.shared::cta;" ::: "memory");
        asm volatile("mbarrier.arrive.expect_tx.shared.b64 _, [%0], %1;"
                     :: "r"(mb), "r"((uint32_t)(LL * 4)) : "memory");
        asm volatile("cp.async.bulk.shared::cta.global.mbarrier::complete_tx::bytes "
                     "[%0], [%1], %2, [%3];"
                     :: "r"(smem_u32(s_rel)), "l"(relb),
                        "r"((uint32_t)(LL * 4)), "r"(mb) : "memory");
    }

    // ---- phase 1a: warp-coalesced gather into smem (lane = region slot) ----
    {
        int p0 = lane / RS,  q0 = lane - RS * p0;
        int s1 = lane + 32;
        int p1 = s1 / RS,    q1 = s1 - RS * p1;
        float cy0 = xval(p0), cx0 = xval(q0);
        float cy1 = xval(p1), cx1 = xval(q1);
        bool  hi_ok = (lane < 17);

        float sf0 = sf[b * 2 + 0], sf1 = sf[b * 2 + 1];
        float bx  = bbox[b * 4 + 0], by = bbox[b * 4 + 1];
        const float* dimg = depth + (size_t)b * IMG * IMG;

#pragma unroll 1
        for (int i = 0; i < 17; i++) {
            int l = wid * 17 + i;                 // wid<4 -> l in [0,68)
            float2 lxy = *reinterpret_cast<const float2*>(
                lm + ((size_t)b * LNUM + l) * 2);
            float fx = (lxy.x - bx) * sf0 / 224.0f * 2.0f - 1.0f;
            float fy = (lxy.y - by) * sf1 / 224.0f * 2.0f - 1.0f;
            float v0 = sample(dimg, fx, fy, cx0, cy0);
            s_reg[l * R2 + lane] = v0;            // lanes 32..48 handled below
            if (hi_ok) {
                float v1 = sample(dimg, fx, fy, cx1, cy1);
                s_reg[l * R2 + lane + 32] = v1;
            }
        }
    }
    __syncthreads();

    // ---- phase 1b: thread-per-landmark register sort (no collectives) ----
    if (tid < LNUM) {
        float v[R2];
        int   k = 0;
#pragma unroll
        for (int i = 0; i < R2; i++) {
            float x = s_reg[tid * R2 + i];
            v[i] = x;
            k += (x <= 1e-4f) ? 1 : 0;
        }

        // Batcher odd-even merge sort, n=64 network pruned to 49 live slots
        // (skipped exchanges pair with implicit +INF -> no-ops). Compile-time
        // indices -> pure register sort.
#pragma unroll
        for (int p = 1; p < 64; p <<= 1) {
#pragma unroll
            for (int kk = p; kk >= 1; kk >>= 1) {
#pragma unroll
                for (int j = kk & (p - 1); j + kk < 64; j += 2 * kk) {
#pragma unroll
                    for (int i = 0; i < kk; i++) {
                        if (i + j + kk < R2) {
                            if ((i + j) / (2 * p) == (i + j + kk) / (2 * p)) {
                                float a  = v[i + j];
                                float bb = v[i + j + kk];
                                v[i + j]      = fminf(a, bb);
                                v[i + j + kk] = fmaxf(a, bb);
                            }
                        }
                    }
                }
            }
        }

        // median rank: mi = (clamp(k,1,48)+48)/2 in [24,48]
        int st = min(max(k, 1), R2 - 1);
        int mi = (st + R2 - 1) >> 1;
        float r = v[24];
#pragma unroll
        for (int i = 25; i < R2; i++) r = (mi >= i) ? v[i] : r;
        smed[tid] = r;
    }
    __syncthreads();

    // ---- phase 2: lower median-of-medians (rank 33) + mask + count ----
    float vraw = 0.0f;
    if (tid < LNUM) {
        vraw = smed[tid];
        int r = 0;
#pragma unroll 4
        for (int j = 0; j < LNUM; j++) {
            float w = smed[j];
            r += (w < vraw || (w == vraw && j < tid)) ? 1 : 0;  // stable rank
        }
        if (r == (LNUM - 1) / 2) s_mom = vraw;
    }
    __syncthreads();
    bool mbit = false;
    if (tid < LNUM) {
        mbit = fabsf(vraw - s_mom) < (90.0f / 500.0f);
        s_mm[tid] = make_float2(vraw * 500.0f, mbit ? 1.0f : 0.0f);
    }
    unsigned bal = __ballot_sync(FULLM, mbit);
    if (lane == 0 && wid < 3) s_cnt[wid] = __popc(bal);
    __syncthreads();

    // ---- wait for staged rel (TRYWAIT fast path, normally complete) ----
    {
        uint32_t done;
        do {
            asm volatile(
                "{\n\t.reg .pred p;\n\t"
                "mbarrier.try_wait.parity.acquire.cta.shared::cta.b64 p, [%1], %2;\n\t"
                "selp.b32 %0, 1, 0, p;\n\t}"
                : "=r"(done) : "r"(mb), "r"(0u) : "memory");
        } while (!done);
    }

    // ---- phase 3: pairwise diff / mask / smooth-L1, float4 stores ----
    // out[0]=loss, outd=out+1, outm=out+1+BS*LL. outd[base+e] has global float
    // index 1+base+e; base%4==0 so e≡3 (mod 4) gives 16B-aligned float4 stores.
    float* outd = out + 1;
    float* outm = out + 1 + (size_t)BS * LL;
    float accL = 0.0f;

    if (tid < 4) {                      // head e=0,1,2 and tail e=4623
        int e = (tid < 3) ? tid : (LL - 1);
        int i = e / LNUM;
        int j = e - i * LNUM;
        float2 mi2 = s_mm[i];
        float2 mj2 = s_mm[j];
        float diff = mi2.x - mj2.x;
        float mk   = mi2.y * mj2.y;
        float d    = s_rel[e] - diff;
        float ad   = fabsf(d);
        float c    = fminf(ad, 1.0f);
        float le   = c * (ad - 0.5f * c);
        outd[base + e] = diff;
        outm[base + e] = mk;
        accL += le * mk;
    }

    for (int g = tid; g < NGRP; g += NTHR) {
        int e0 = 3 + (g << 2);
        int i0 = e0 / LNUM;
        int j0 = e0 - i0 * LNUM;
        float dvv[4], mvv[4];
#pragma unroll
        for (int n = 0; n < 4; n++) {
            int jn = j0 + n;
            int wrap = (jn >= LNUM) ? 1 : 0;
            int in = i0 + wrap;
            jn -= LNUM * wrap;
            float2 mi2 = s_mm[in];
            float2 mj2 = s_mm[jn];
            float diff = mi2.x - mj2.x;
            float mk   = mi2.y * mj2.y;
            float d    = s_rel[e0 + n] - diff;
            float ad   = fabsf(d);
            float c    = fminf(ad, 1.0f);
            float le   = c * (ad - 0.5f * c);
            dvv[n] = diff;
            mvv[n] = mk;
            accL += le * mk;
        }
        *reinterpret_cast<float4*>(outd + base + e0) =
            make_float4(dvv[0], dvv[1], dvv[2], dvv[3]);
        *reinterpret_cast<float4*>(outm + base + e0) =
            make_float4(mvv[0], mvv[1], mvv[2], mvv[3]);
    }

    // ---- block reduce + global atomics + last-block finalize ----
    double dL = (double)accL;
#pragma unroll
    for (int o = 16; o > 0; o >>= 1)
        dL += __shfl_down_sync(FULLM, dL, o);
    if (lane == 0) redL[wid] = dL;
    __syncthreads();
    if (tid == 0) {
        double tL = 0.0;
#pragma unroll
        for (int w = 0; w < NWARP; w++) tL += redL[w];
        double cnt = (double)(s_cnt[0] + s_cnt[1] + s_cnt[2]);
        atomicAdd(&g_sumL, tL);
        atomicAdd(&g_sumM, cnt * cnt);      // sum_ij mi*mj == (sum m)^2
        __threadfence();
        unsigned n = atomicAdd(&g_done, 1u);
        s_last = (n == BS - 1);
    }
    __syncthreads();

    if (s_last && tid == 0) {
        __threadfence();
        double L = g_sumL, M = g_sumM;
        out[0] = (float)(L / (M + 1e-4));
        g_sumL = 0.0; g_sumM = 0.0; g_done = 0u;
    }
}

extern "C" void kernel_launch(void* const* d_in, const int* in_sizes, int n_in,
                              void* d_out, int out_size)
{
    const float* rel   = (const float*)d_in[0];   // [BS, L, L]
    const float* depth = (const float*)d_in[1];   // [BS, 1, IMG, IMG]
    const float* lm    = (const float*)d_in[2];   // [BS, L, 2]
    const float* sf    = (const float*)d_in[3];   // [BS, 2]
    const float* bbox  = (const float*)d_in[4];   // [BS, 4]
    float* out = (float*)d_out;                   // [loss | diff | mask]

    fused_kernel<<<BS, NTHR>>>(rel, depth, lm, sf, bbox, out);
}

// round 12
// speedup vs baseline: 1.0919x; 1.0919x over previous
#include <cuda_runtime.h>
#include <math.h>
#include <stdint.h>

#define BS    512
#define LNUM  68
#define IMG   224
#define RS    7
#define R2    49
#define LL    (LNUM * LNUM)     // 4624
#define NLM   (BS * LNUM)
#define FULLM 0xFFFFFFFFu
#define NGRP  ((LL - 4) / 4)    // 1155 float4 store groups per batch
#define K2_BLOCKS (BS * 2)
#define K2_THREADS 256
#define HALF0 578               // groups [0,578) / [578,1155)

__device__ __align__(16) float2 g_mm[NLM];   // (med*500, mask)
__device__ float  g_cnt[BS];
__device__ double g_partL[K2_BLOCKS];

// linspace(-3.5,3.5,7)[k] / 224 * 2 — identical op order to the reference.
__device__ __forceinline__ float xval(int k) {
    float x = -3.5f + (float)k * (7.0f / 6.0f);
    if (k == RS - 1) x = 3.5f;
    return x / 224.0f * 2.0f;
}

// One region sample; exact replica of the reference's grid_sample-nearest
// arithmetic (rintf == jnp.round, half-even).
__device__ __forceinline__ float sample(const float* __restrict__ dimg,
                                        float fx, float fy, float cx, float cy)
{
    float gy = fy + cy;
    float gx = fx + cx;
    float iy = ((gy + 1.0f) * 224.0f - 1.0f) * 0.5f;
    float ix = ((gx + 1.0f) * 224.0f - 1.0f) * 0.5f;
    int yi = (int)rintf(iy);
    int xi = (int)rintf(ix);
    bool v = (yi >= 0) & (yi < IMG) & (xi >= 0) & (xi < IMG);
    int yc = min(max(yi, 0), IMG - 1);
    int xc = min(max(xi, 0), IMG - 1);
    float val = __ldg(dimg + yc * IMG + xc);
    return v ? val : 0.0f;
}

// ---- K1: one block per batch. Coalesced gather -> smem -> register sort ----
__global__ __launch_bounds__(128, 4) void k1_medians(
    const float* __restrict__ depth,
    const float* __restrict__ lm,
    const float* __restrict__ sf,
    const float* __restrict__ bbox)
{
    __shared__ float s_reg[LNUM * R2];       // 13328 B, stride 49 -> conflict-free
    __shared__ __align__(16) float smed[LNUM];
    __shared__ float s_mom;
    __shared__ int   s_pc[4];

    int b    = blockIdx.x;
    int tid  = threadIdx.x;
    int wid  = tid >> 5;
    int lane = tid & 31;

    // gather: warp w -> landmarks w*17 .. w*17+16, lane = region slot
    {
        int p0 = lane / RS,  q0 = lane - RS * p0;
        int s1 = lane + 32;
        int p1 = s1 / RS,    q1 = s1 - RS * p1;
        float cy0 = xval(p0), cx0 = xval(q0);
        float cy1 = xval(p1), cx1 = xval(q1);
        bool  hi_ok = (lane < 17);

        float sf0 = sf[b * 2 + 0], sf1 = sf[b * 2 + 1];
        float bx  = bbox[b * 4 + 0], by = bbox[b * 4 + 1];
        const float* dimg = depth + (size_t)b * IMG * IMG;

#pragma unroll 1
        for (int i = 0; i < 17; i++) {
            int l = wid * 17 + i;
            float2 lxy = *reinterpret_cast<const float2*>(
                lm + ((size_t)b * LNUM + l) * 2);
            float fx = (lxy.x - bx) * sf0 / 224.0f * 2.0f - 1.0f;
            float fy = (lxy.y - by) * sf1 / 224.0f * 2.0f - 1.0f;
            float v0 = sample(dimg, fx, fy, cx0, cy0);
            s_reg[l * R2 + lane] = v0;
            if (hi_ok) {
                float v1 = sample(dimg, fx, fy, cx1, cy1);
                s_reg[l * R2 + lane + 32] = v1;
            }
        }
    }
    __syncthreads();

    // thread-per-landmark register sort (no collectives, indices compile-time)
    if (tid < LNUM) {
        float v[R2];
        int   k = 0;
#pragma unroll
        for (int i = 0; i < R2; i++) {
            float x = s_reg[tid * R2 + i];
            v[i] = x;
            k += (x <= 1e-4f) ? 1 : 0;
        }
        // Batcher odd-even merge sort, n=64 pruned to 49 live slots
#pragma unroll
        for (int p = 1; p < 64; p <<= 1) {
#pragma unroll
            for (int kk = p; kk >= 1; kk >>= 1) {
#pragma unroll
                for (int j = kk & (p - 1); j + kk < 64; j += 2 * kk) {
#pragma unroll
                    for (int i = 0; i < kk; i++) {
                        if (i + j + kk < R2 &&
                            (i + j) / (2 * p) == (i + j + kk) / (2 * p)) {
                            float a  = v[i + j];
                            float bb = v[i + j + kk];
                            v[i + j]      = fminf(a, bb);
                            v[i + j + kk] = fmaxf(a, bb);
                        }
                    }
                }
            }
        }
        // region median: rank mi = (clamp(count<=THR,1,48)+48)/2 in [24,48]
        int st = min(max(k, 1), R2 - 1);
        int mi = (st + R2 - 1) >> 1;
        float r = v[24];
#pragma unroll
        for (int i = 25; i < R2; i++) r = (mi >= i) ? v[i] : r;
        smed[tid] = r;
    }
    __syncthreads();

    // lower median-of-medians (rank 33), float4-vectorized stable rank count
    float vraw = 0.0f;
    if (tid < LNUM) {
        vraw = smed[tid];
        const float4* m4 = reinterpret_cast<const float4*>(smed);
        int r = 0;
#pragma unroll
        for (int jj = 0; jj < LNUM / 4; jj++) {
            float4 w = m4[jj];
            int j0 = jj * 4;
            r += (w.x < vraw || (w.x == vraw && j0 + 0 < tid)) ? 1 : 0;
            r += (w.y < vraw || (w.y == vraw && j0 + 1 < tid)) ? 1 : 0;
            r += (w.z < vraw || (w.z == vraw && j0 + 2 < tid)) ? 1 : 0;
            r += (w.w < vraw || (w.w == vraw && j0 + 3 < tid)) ? 1 : 0;
        }
        if (r == (LNUM - 1) / 2) s_mom = vraw;
    }
    __syncthreads();

    bool mbit = (tid < LNUM) && (fabsf(vraw - s_mom) < (90.0f / 500.0f));
    if (tid < LNUM)
        g_mm[b * LNUM + tid] = make_float2(vraw * 500.0f, mbit ? 1.0f : 0.0f);
    unsigned bal = __ballot_sync(FULLM, mbit);
    if (lane == 0) s_pc[wid] = __popc(bal);
    __syncthreads();
    if (tid == 0)
        g_cnt[b] = (float)(s_pc[0] + s_pc[1] + s_pc[2] + s_pc[3]);
}

// ---- K2: streaming pairwise loss, 2 blocks per batch, no atomics ----------
__global__ __launch_bounds__(K2_THREADS) void k2_pairwise(
    const float* __restrict__ rel,
    float* __restrict__ out)
{
    __shared__ __align__(16) float2 s_mm[LNUM];
    __shared__ double redL[K2_THREADS / 32];

    int blk  = blockIdx.x;
    int b    = blk >> 1;
    int half = blk & 1;
    int tid  = threadIdx.x;
    int wid  = tid >> 5;
    int lane = tid & 31;

    if (tid < LNUM / 2)                      // 34 float4 = 68 float2
        reinterpret_cast<float4*>(s_mm)[tid] =
            reinterpret_cast<const float4*>(g_mm + b * LNUM)[tid];
    __syncthreads();

    const size_t base = (size_t)b * LL;
    const float* relb = rel + base;
    float* outd = out + 1;
    float* outm = out + 1 + (size_t)BS * LL;
    float accL = 0.0f;

    // head e=0,1,2 (half 0) and tail e=4623 (half 1); float4 body e=3+4g.
    if (half == 0 ? (tid < 3) : (tid == 0)) {
        int e = (half == 0) ? tid : (LL - 1);
        int i = e / LNUM;
        int j = e - i * LNUM;
        float2 mi2 = s_mm[i];
        float2 mj2 = s_mm[j];
        float diff = mi2.x - mj2.x;
        float mk   = mi2.y * mj2.y;
        float d    = __ldg(relb + e) - diff;
        float ad   = fabsf(d);
        float c    = fminf(ad, 1.0f);
        float le   = c * (ad - 0.5f * c);
        outd[base + e] = diff;
        outm[base + e] = mk;
        accL += le * mk;
    }

    int gstart = half ? HALF0 : 0;
    int gend   = half ? NGRP : HALF0;
    for (int g = gstart + tid; g < gend; g += K2_THREADS) {
        int e0 = 3 + (g << 2);
        int i0 = e0 / LNUM;
        int j0 = e0 - i0 * LNUM;
        float dvv[4], mvv[4];
#pragma unroll
        for (int n = 0; n < 4; n++) {
            int jn = j0 + n;
            int wrap = (jn >= LNUM) ? 1 : 0;
            int in = i0 + wrap;
            jn -= LNUM * wrap;
            float2 mi2 = s_mm[in];
            float2 mj2 = s_mm[jn];
            float diff = mi2.x - mj2.x;
            float mk   = mi2.y * mj2.y;
            float d    = __ldg(relb + e0 + n) - diff;
            float ad   = fabsf(d);
            float c    = fminf(ad, 1.0f);
            float le   = c * (ad - 0.5f * c);
            dvv[n] = diff;
            mvv[n] = mk;
            accL += le * mk;
        }
        *reinterpret_cast<float4*>(outd + base + e0) =
            make_float4(dvv[0], dvv[1], dvv[2], dvv[3]);
        *reinterpret_cast<float4*>(outm + base + e0) =
            make_float4(mvv[0], mvv[1], mvv[2], mvv[3]);
    }

    double dL = (double)accL;
#pragma unroll
    for (int o = 16; o > 0; o >>= 1)
        dL += __shfl_down_sync(FULLM, dL, o);
    if (lane == 0) redL[wid] = dL;
    __syncthreads();
    if (tid == 0) {
        double tL = 0.0;
#pragma unroll
        for (int w = 0; w < K2_THREADS / 32; w++) tL += redL[w];
        g_partL[blk] = tL;                   // plain store, no atomics
    }
}

// ---- K3: final reduction -> loss scalar -----------------------------------
__global__ __launch_bounds__(512) void k3_final(float* __restrict__ out)
{
    __shared__ double rL[16], rM[16];
    int tid  = threadIdx.x;
    int wid  = tid >> 5;
    int lane = tid & 31;

    double L = 0.0, M = 0.0;
    for (int i = tid; i < K2_BLOCKS; i += 512) L += g_partL[i];
    for (int b = tid; b < BS; b += 512) {
        double c = (double)g_cnt[b];
        M += c * c;                          // sum_ij mi*mj == (sum m)^2
    }
#pragma unroll
    for (int o = 16; o > 0; o >>= 1) {
        L += __shfl_down_sync(FULLM, L, o);
        M += __shfl_down_sync(FULLM, M, o);
    }
    if (lane == 0) { rL[wid] = L; rM[wid] = M; }
    __syncthreads();
    if (wid == 0) {
        double vL = (lane < 16) ? rL[lane] : 0.0;
        double vM = (lane < 16) ? rM[lane] : 0.0;
#pragma unroll
        for (int o = 8; o > 0; o >>= 1) {
            vL += __shfl_down_sync(FULLM, vL, o);
            vM += __shfl_down_sync(FULLM, vM, o);
        }
        if (lane == 0) out[0] = (float)(vL / (vM + 1e-4));
    }
}

extern "C" void kernel_launch(void* const* d_in, const int* in_sizes, int n_in,
                              void* d_out, int out_size)
{
    const float* rel   = (const float*)d_in[0];   // [BS, L, L]
    const float* depth = (const float*)d_in[1];   // [BS, 1, IMG, IMG]
    const float* lm    = (const float*)d_in[2];   // [BS, L, 2]
    const float* sf    = (const float*)d_in[3];   // [BS, 2]
    const float* bbox  = (const float*)d_in[4];   // [BS, 4]
    float* out = (float*)d_out;                   // [loss | diff | mask]

    k1_medians<<<BS, 128>>>(depth, lm, sf, bbox);
    k2_pairwise<<<K2_BLOCKS, K2_THREADS>>>(rel, out);
    k3_final<<<1, 512>>>(out);
}

// round 13
// speedup vs baseline: 1.4086x; 1.2900x over previous
#include <cuda_runtime.h>
#include <math.h>
#include <stdint.h>

#define BS    512
#define LNUM  68
#define IMG   224
#define RS    7
#define R2    49
#define LL    (LNUM * LNUM)     // 4624
#define NLM   (BS * LNUM)
#define FULLM 0xFFFFFFFFu
#define NGRP  ((LL - 4) / 4)    // 1155 float4 store groups per batch
#define K2_BLOCKS (BS * 2)
#define K2_THREADS 256
#define HALF0 578               // groups [0,578) / [578,1155)

__device__ __align__(16) float2 g_mm[NLM];   // (med*500, mask)
__device__ float  g_cnt[BS];
__device__ double g_partL[K2_BLOCKS];

// linspace(-3.5,3.5,7)[k] / 224 * 2 — identical op order to the reference.
__device__ __forceinline__ float xval(int k) {
    float x = -3.5f + (float)k * (7.0f / 6.0f);
    if (k == RS - 1) x = 3.5f;
    return x / 224.0f * 2.0f;
}

// One region sample; exact replica of the reference's grid_sample-nearest
// arithmetic (rintf == jnp.round, half-even).
__device__ __forceinline__ float sample(const float* __restrict__ dimg,
                                        float fx, float fy, float cx, float cy)
{
    float gy = fy + cy;
    float gx = fx + cx;
    float iy = ((gy + 1.0f) * 224.0f - 1.0f) * 0.5f;
    float ix = ((gx + 1.0f) * 224.0f - 1.0f) * 0.5f;
    int yi = (int)rintf(iy);
    int xi = (int)rintf(ix);
    bool v = (yi >= 0) & (yi < IMG) & (xi >= 0) & (xi < IMG);
    int yc = min(max(yi, 0), IMG - 1);
    int xc = min(max(xi, 0), IMG - 1);
    float val = __ldg(dimg + yc * IMG + xc);
    return v ? val : 0.0f;
}

// ---- K1: one block (512 thr) per batch. High-MLP coalesced gather -> smem
// -> thread-per-landmark register sort -> median-of-medians -> g_mm/g_cnt.
__global__ __launch_bounds__(512) void k1_medians(
    const float* __restrict__ depth,
    const float* __restrict__ lm,
    const float* __restrict__ sf,
    const float* __restrict__ bbox)
{
    __shared__ float s_reg[LNUM * R2];       // 13328 B, stride 49 -> conflict-free
    __shared__ __align__(16) float smed[LNUM];
    __shared__ float s_mom;
    __shared__ int   s_pc[3];

    int b    = blockIdx.x;
    int tid  = threadIdx.x;
    int wid  = tid >> 5;                     // 0..15
    int lane = tid & 31;

    // ---- gather: warp w -> landmarks {w, w+16, w+32, w+48, w+64(if w<4)} ----
    {
        int p0 = lane / RS,  q0 = lane - RS * p0;
        int s1 = lane + 32;
        int p1 = s1 / RS,    q1 = s1 - RS * p1;
        float cy0 = xval(p0), cx0 = xval(q0);
        float cy1 = xval(p1), cx1 = xval(q1);
        bool  hi_ok = (lane < 17);

        float sf0 = sf[b * 2 + 0], sf1 = sf[b * 2 + 1];
        float bx  = bbox[b * 4 + 0], by = bbox[b * 4 + 1];
        const float* dimg = depth + (size_t)b * IMG * IMG;

        int nl = (wid < 4) ? 5 : 4;
        float2 lxy[5];
#pragma unroll
        for (int i = 0; i < 5; i++) {        // prefetch all lm loads (MLP)
            int l = wid + 16 * i;
            if (i < nl)
                lxy[i] = *reinterpret_cast<const float2*>(
                    lm + ((size_t)b * LNUM + l) * 2);
        }
#pragma unroll
        for (int i = 0; i < 5; i++) {        // all depth LDGs independent
            if (i < nl) {
                int l = wid + 16 * i;
                float fx = (lxy[i].x - bx) * sf0 / 224.0f * 2.0f - 1.0f;
                float fy = (lxy[i].y - by) * sf1 / 224.0f * 2.0f - 1.0f;
                float v0 = sample(dimg, fx, fy, cx0, cy0);
                s_reg[l * R2 + lane] = v0;
                if (hi_ok) {
                    float v1 = sample(dimg, fx, fy, cx1, cy1);
                    s_reg[l * R2 + lane + 32] = v1;
                }
            }
        }
    }
    __syncthreads();

    // ---- thread-per-landmark register sort (no collectives) ----
    if (tid < LNUM) {
        float v[R2];
        int   k = 0;
#pragma unroll
        for (int i = 0; i < R2; i++) {
            float x = s_reg[tid * R2 + i];
            v[i] = x;
            k += (x <= 1e-4f) ? 1 : 0;
        }
        // Batcher odd-even merge sort, n=64 pruned to 49 live slots
#pragma unroll
        for (int p = 1; p < 64; p <<= 1) {
#pragma unroll
            for (int kk = p; kk >= 1; kk >>= 1) {
#pragma unroll
                for (int j = kk & (p - 1); j + kk < 64; j += 2 * kk) {
#pragma unroll
                    for (int i = 0; i < kk; i++) {
                        if (i + j + kk < R2 &&
                            (i + j) / (2 * p) == (i + j + kk) / (2 * p)) {
                            float a  = v[i + j];
                            float bb = v[i + j + kk];
                            v[i + j]      = fminf(a, bb);
                            v[i + j + kk] = fmaxf(a, bb);
                        }
                    }
                }
            }
        }
        // region median: rank mi = (clamp(count<=THR,1,48)+48)/2 in [24,48]
        int st = min(max(k, 1), R2 - 1);
        int mi = (st + R2 - 1) >> 1;
        float r = v[24];
#pragma unroll
        for (int i = 25; i < R2; i++) r = (mi >= i) ? v[i] : r;
        smed[tid] = r;
    }
    __syncthreads();

    // ---- lower median-of-medians (rank 33), vectorized stable rank count ----
    float vraw = 0.0f;
    if (tid < LNUM) {
        vraw = smed[tid];
        const float4* m4 = reinterpret_cast<const float4*>(smed);
        int r = 0;
#pragma unroll
        for (int jj = 0; jj < LNUM / 4; jj++) {
            float4 w = m4[jj];
            int j0 = jj * 4;
            r += (w.x < vraw || (w.x == vraw && j0 + 0 < tid)) ? 1 : 0;
            r += (w.y < vraw || (w.y == vraw && j0 + 1 < tid)) ? 1 : 0;
            r += (w.z < vraw || (w.z == vraw && j0 + 2 < tid)) ? 1 : 0;
            r += (w.w < vraw || (w.w == vraw && j0 + 3 < tid)) ? 1 : 0;
        }
        if (r == (LNUM - 1) / 2) s_mom = vraw;
    }
    __syncthreads();

    bool mbit = (tid < LNUM) && (fabsf(vraw - s_mom) < (90.0f / 500.0f));
    if (tid < LNUM)
        g_mm[b * LNUM + tid] = make_float2(vraw * 500.0f, mbit ? 1.0f : 0.0f);
    unsigned bal = __ballot_sync(FULLM, mbit);
    if (lane == 0 && wid < 3) s_pc[wid] = __popc(bal);
    __syncthreads();
    if (tid == 0)
        g_cnt[b] = (float)(s_pc[0] + s_pc[1] + s_pc[2]);
}

// ---- K2: streaming pairwise loss, 2 blocks per batch, no atomics ----------
__global__ __launch_bounds__(K2_THREADS) void k2_pairwise(
    const float* __restrict__ rel,
    float* __restrict__ out)
{
    __shared__ __align__(16) float2 s_mm[LNUM];
    __shared__ double redL[K2_THREADS / 32];

    int blk  = blockIdx.x;
    int b    = blk >> 1;
    int half = blk & 1;
    int tid  = threadIdx.x;
    int wid  = tid >> 5;
    int lane = tid & 31;

    if (tid < LNUM / 2)                      // 34 float4 = 68 float2
        reinterpret_cast<float4*>(s_mm)[tid] =
            reinterpret_cast<const float4*>(g_mm + b * LNUM)[tid];
    __syncthreads();

    const size_t base = (size_t)b * LL;
    const float* relb = rel + base;
    float* outd = out + 1;
    float* outm = out + 1 + (size_t)BS * LL;
    float accL = 0.0f;

    // head e=0,1,2 (half 0) and tail e=4623 (half 1); float4 body e=3+4g.
    if (half == 0 ? (tid < 3) : (tid == 0)) {
        int e = (half == 0) ? tid : (LL - 1);
        int i = e / LNUM;
        int j = e - i * LNUM;
        float2 mi2 = s_mm[i];
        float2 mj2 = s_mm[j];
        float diff = mi2.x - mj2.x;
        float mk   = mi2.y * mj2.y;
        float d    = __ldg(relb + e) - diff;
        float ad   = fabsf(d);
        float c    = fminf(ad, 1.0f);
        float le   = c * (ad - 0.5f * c);
        outd[base + e] = diff;
        outm[base + e] = mk;
        accL += le * mk;
    }

    int gstart = half ? HALF0 : 0;
    int gend   = half ? NGRP : HALF0;
    for (int g = gstart + tid; g < gend; g += K2_THREADS) {
        int e0 = 3 + (g << 2);
        int i0 = e0 / LNUM;
        int j0 = e0 - i0 * LNUM;
        float dvv[4], mvv[4];
#pragma unroll
        for (int n = 0; n < 4; n++) {
            int jn = j0 + n;
            int wrap = (jn >= LNUM) ? 1 : 0;
            int in = i0 + wrap;
            jn -= LNUM * wrap;
            float2 mi2 = s_mm[in];
            float2 mj2 = s_mm[jn];
            float diff = mi2.x - mj2.x;
            float mk   = mi2.y * mj2.y;
            float d    = __ldg(relb + e0 + n) - diff;
            float ad   = fabsf(d);
            float c    = fminf(ad, 1.0f);
            float le   = c * (ad - 0.5f * c);
            dvv[n] = diff;
            mvv[n] = mk;
            accL += le * mk;
        }
        *reinterpret_cast<float4*>(outd + base + e0) =
            make_float4(dvv[0], dvv[1], dvv[2], dvv[3]);
        *reinterpret_cast<float4*>(outm + base + e0) =
            make_float4(mvv[0], mvv[1], mvv[2], mvv[3]);
    }

    double dL = (double)accL;
#pragma unroll
    for (int o = 16; o > 0; o >>= 1)
        dL += __shfl_down_sync(FULLM, dL, o);
    if (lane == 0) redL[wid] = dL;
    __syncthreads();
    if (tid == 0) {
        double tL = 0.0;
#pragma unroll
        for (int w = 0; w < K2_THREADS / 32; w++) tL += redL[w];
        g_partL[blk] = tL;                   // plain store, no atomics
    }
}

// ---- K3: final reduction -> loss scalar -----------------------------------
__global__ __launch_bounds__(512) void k3_final(float* __restrict__ out)
{
    __shared__ double rL[16], rM[16];
    int tid  = threadIdx.x;
    int wid  = tid >> 5;
    int lane = tid & 31;

    double L = 0.0, M = 0.0;
    for (int i = tid; i < K2_BLOCKS; i += 512) L += g_partL[i];
    for (int b = tid; b < BS; b += 512) {
        double c = (double)g_cnt[b];
        M += c * c;                          // sum_ij mi*mj == (sum m)^2
    }
#pragma unroll
    for (int o = 16; o > 0; o >>= 1) {
        L += __shfl_down_sync(FULLM, L, o);
        M += __shfl_down_sync(FULLM, M, o);
    }
    if (lane == 0) { rL[wid] = L; rM[wid] = M; }
    __syncthreads();
    if (wid == 0) {
        double vL = (lane < 16) ? rL[lane] : 0.0;
        double vM = (lane < 16) ? rM[lane] : 0.0;
#pragma unroll
        for (int o = 8; o > 0; o >>= 1) {
            vL += __shfl_down_sync(FULLM, vL, o);
            vM += __shfl_down_sync(FULLM, vM, o);
        }
        if (lane == 0) out[0] = (float)(vL / (vM + 1e-4));
    }
}

extern "C" void kernel_launch(void* const* d_in, const int* in_sizes, int n_in,
                              void* d_out, int out_size)
{
    const float* rel   = (const float*)d_in[0];   // [BS, L, L]
    const float* depth = (const float*)d_in[1];   // [BS, 1, IMG, IMG]
    const float* lm    = (const float*)d_in[2];   // [BS, L, 2]
    const float* sf    = (const float*)d_in[3];   // [BS, 2]
    const float* bbox  = (const float*)d_in[4];   // [BS, 4]
    float* out = (float*)d_out;                   // [loss | diff | mask]

    k1_medians<<<BS, 512>>>(depth, lm, sf, bbox);
    k2_pairwise<<<K2_BLOCKS, K2_THREADS>>>(rel, out);
    k3_final<<<1, 512>>>(out);
}

// round 14
// speedup vs baseline: 1.6689x; 1.1848x over previous
#include <cuda_runtime.h>
#include <math.h>
#include <stdint.h>

#define BS    512
#define LNUM  68
#define IMG   224
#define RS    7
#define R2    49
#define LL    (LNUM * LNUM)     // 4624
#define NLM   (BS * LNUM)
#define FULLM 0xFFFFFFFFu
#define NGRP  ((LL - 4) / 4)    // 1155 float4 store groups per batch
#define K2_BLOCKS (BS * 2)
#define K2_THREADS 256
#define HALF0 578               // groups [0,578) / [578,1155)

__device__ __align__(16) float2 g_mm[NLM];   // (med*500, mask)
__device__ float  g_cnt[BS];
__device__ double g_partL[K2_BLOCKS];

// linspace(-3.5,3.5,7)[k] / 224 * 2 — identical op order to the reference.
__device__ __forceinline__ float xval(int k) {
    float x = -3.5f + (float)k * (7.0f / 6.0f);
    if (k == RS - 1) x = 3.5f;
    return x / 224.0f * 2.0f;
}

// One region sample; exact replica of the reference's grid_sample-nearest
// arithmetic (rintf == jnp.round, half-even).
__device__ __forceinline__ float sample(const float* __restrict__ dimg,
                                        float fx, float fy, float cx, float cy)
{
    float gy = fy + cy;
    float gx = fx + cx;
    float iy = ((gy + 1.0f) * 224.0f - 1.0f) * 0.5f;
    float ix = ((gx + 1.0f) * 224.0f - 1.0f) * 0.5f;
    int yi = (int)rintf(iy);
    int xi = (int)rintf(ix);
    bool v = (yi >= 0) & (yi < IMG) & (xi >= 0) & (xi < IMG);
    int yc = min(max(yi, 0), IMG - 1);
    int xc = min(max(xi, 0), IMG - 1);
    float val = __ldg(dimg + yc * IMG + xc);
    return v ? val : 0.0f;
}

// Pruned Batcher odd-even merge sort: sorts first NLIVE of a virtual n=32
// array (pruned CEs pair with implicit +INF -> no-ops). Compile-time indices
// -> pure register sort, <= NLIVE live values.
template<int NLIVE>
__device__ __forceinline__ void regsort(float (&v)[25])
{
#pragma unroll
    for (int p = 1; p < 32; p <<= 1) {
#pragma unroll
        for (int kk = p; kk >= 1; kk >>= 1) {
#pragma unroll
            for (int j = kk & (p - 1); j + kk < 32; j += 2 * kk) {
#pragma unroll
                for (int i = 0; i < kk; i++) {
                    if (i + j + kk < NLIVE &&
                        (i + j) / (2 * p) == (i + j + kk) / (2 * p)) {
                        float a  = v[i + j];
                        float bb = v[i + j + kk];
                        v[i + j]      = fminf(a, bb);
                        v[i + j + kk] = fmaxf(a, bb);
                    }
                }
            }
        }
    }
}

// ---- K1: one block (512 thr) per batch. High-MLP coalesced gather -> smem
// -> per-thread two-half register sort (<=25 live, no spill) + rank binary
// search -> median-of-medians -> g_mm / g_cnt.
__global__ __launch_bounds__(512) void k1_medians(
    const float* __restrict__ depth,
    const float* __restrict__ lm,
    const float* __restrict__ sf,
    const float* __restrict__ bbox)
{
    __shared__ float s_reg[LNUM * R2];       // 13328 B, stride 49 -> conflict-free
    __shared__ int   s_k[LNUM];              // per-landmark count(v <= THR)
    __shared__ __align__(16) float smed[LNUM];
    __shared__ float s_mom;
    __shared__ int   s_pc[3];

    int b    = blockIdx.x;
    int tid  = threadIdx.x;
    int wid  = tid >> 5;                     // 0..15
    int lane = tid & 31;

    // ---- gather: warp w -> landmarks {w, w+16, w+32, w+48, w+64(if w<4)} ----
    {
        int p0 = lane / RS,  q0 = lane - RS * p0;
        int s1 = lane + 32;
        int p1 = s1 / RS,    q1 = s1 - RS * p1;
        float cy0 = xval(p0), cx0 = xval(q0);
        float cy1 = xval(p1), cx1 = xval(q1);
        bool  hi_ok = (lane < 17);

        float sf0 = sf[b * 2 + 0], sf1 = sf[b * 2 + 1];
        float bx  = bbox[b * 4 + 0], by = bbox[b * 4 + 1];
        const float* dimg = depth + (size_t)b * IMG * IMG;

        int nl = (wid < 4) ? 5 : 4;          // warp-uniform
        float2 lxy[5];
#pragma unroll
        for (int i = 0; i < 5; i++) {        // prefetch all lm loads (MLP)
            int l = wid + 16 * i;
            if (i < nl)
                lxy[i] = *reinterpret_cast<const float2*>(
                    lm + ((size_t)b * LNUM + l) * 2);
        }
#pragma unroll
        for (int i = 0; i < 5; i++) {
            if (i < nl) {
                int l = wid + 16 * i;
                float fx = (lxy[i].x - bx) * sf0 / 224.0f * 2.0f - 1.0f;
                float fy = (lxy[i].y - by) * sf1 / 224.0f * 2.0f - 1.0f;
                float v0 = sample(dimg, fx, fy, cx0, cy0);
                float v1 = __int_as_float(0x7f800000);
                if (hi_ok) v1 = sample(dimg, fx, fy, cx1, cy1);
                s_reg[l * R2 + lane] = v0;
                if (hi_ok) s_reg[l * R2 + lane + 32] = v1;
                // count k for this landmark (ballots uniform across warp)
                unsigned c0 = __ballot_sync(FULLM, v0 <= 1e-4f);
                unsigned c1 = __ballot_sync(FULLM, hi_ok && (v1 <= 1e-4f));
                if (lane == 0) s_k[l] = __popc(c0) + __popc(c1);
            }
        }
    }
    __syncthreads();

    // ---- per-thread median: sort two halves in place, then rank search ----
    if (tid < LNUM) {
        float* row = &s_reg[tid * R2];
        float v[25];
#pragma unroll
        for (int i = 0; i < 25; i++) v[i] = row[i];
        regsort<25>(v);
#pragma unroll
        for (int i = 0; i < 25; i++) row[i] = v[i];
#pragma unroll
        for (int i = 0; i < 24; i++) v[i] = row[25 + i];
        regsort<24>(v);
#pragma unroll
        for (int i = 0; i < 24; i++) row[25 + i] = v[i];

        // rank mi = (clamp(k,1,48)+48)/2 in [24,48]; k-th of two sorted arrays
        int k  = s_k[tid];
        int st = min(max(k, 1), R2 - 1);
        int mi = (st + R2 - 1) >> 1;

        const float NINF = __int_as_float(0xff800000);
        const float PINF = __int_as_float(0x7f800000);
        int lo = max(0, mi - 24);            // i = #taken from A (size 25)
        int hi = min(mi, 25);
        float ans = 0.0f;
        while (lo <= hi) {
            int i = (lo + hi) >> 1;
            int j = mi - i;                  // from B (size 24)
            float Ai_1 = (i > 0)  ? row[i - 1]      : NINF;
            float Bj_1 = (j > 0)  ? row[25 + j - 1] : NINF;
            float Ai   = (i < 25) ? row[i]          : PINF;
            float Bj   = (j < 24) ? row[25 + j]     : PINF;
            if (Ai_1 > Bj)      hi = i - 1;
            else if (Bj_1 > Ai) lo = i + 1;
            else { ans = fminf(Ai, Bj); break; }
        }
        smed[tid] = ans;
    }
    __syncthreads();

    // ---- lower median-of-medians (rank 33), vectorized stable rank count ----
    float vraw = 0.0f;
    if (tid < LNUM) {
        vraw = smed[tid];
        const float4* m4 = reinterpret_cast<const float4*>(smed);
        int r = 0;
#pragma unroll
        for (int jj = 0; jj < LNUM / 4; jj++) {
            float4 w = m4[jj];
            int j0 = jj * 4;
            r += (w.x < vraw || (w.x == vraw && j0 + 0 < tid)) ? 1 : 0;
            r += (w.y < vraw || (w.y == vraw && j0 + 1 < tid)) ? 1 : 0;
            r += (w.z < vraw || (w.z == vraw && j0 + 2 < tid)) ? 1 : 0;
            r += (w.w < vraw || (w.w == vraw && j0 + 3 < tid)) ? 1 : 0;
        }
        if (r == (LNUM - 1) / 2) s_mom = vraw;
    }
    __syncthreads();

    bool mbit = (tid < LNUM) && (fabsf(vraw - s_mom) < (90.0f / 500.0f));
    if (tid < LNUM)
        g_mm[b * LNUM + tid] = make_float2(vraw * 500.0f, mbit ? 1.0f : 0.0f);
    unsigned bal = __ballot_sync(FULLM, mbit);
    if (lane == 0 && wid < 3) s_pc[wid] = __popc(bal);
    __syncthreads();
    if (tid == 0)
        g_cnt[b] = (float)(s_pc[0] + s_pc[1] + s_pc[2]);
}

// ---- K2: streaming pairwise loss, 2 blocks per batch, no atomics ----------
__global__ __launch_bounds__(K2_THREADS) void k2_pairwise(
    const float* __restrict__ rel,
    float* __restrict__ out)
{
    __shared__ __align__(16) float2 s_mm[LNUM];
    __shared__ double redL[K2_THREADS / 32];

    int blk  = blockIdx.x;
    int b    = blk >> 1;
    int half = blk & 1;
    int tid  = threadIdx.x;
    int wid  = tid >> 5;
    int lane = tid & 31;

    if (tid < LNUM / 2)                      // 34 float4 = 68 float2
        reinterpret_cast<float4*>(s_mm)[tid] =
            reinterpret_cast<const float4*>(g_mm + b * LNUM)[tid];
    __syncthreads();

    const size_t base = (size_t)b * LL;
    const float* relb = rel + base;
    float* outd = out + 1;
    float* outm = out + 1 + (size_t)BS * LL;
    float accL = 0.0f;

    // head e=0,1,2 (half 0) and tail e=4623 (half 1); float4 body e=3+4g.
    if (half == 0 ? (tid < 3) : (tid == 0)) {
        int e = (half == 0) ? tid : (LL - 1);
        int i = e / LNUM;
        int j = e - i * LNUM;
        float2 mi2 = s_mm[i];
        float2 mj2 = s_mm[j];
        float diff = mi2.x - mj2.x;
        float mk   = mi2.y * mj2.y;
        float d    = __ldg(relb + e) - diff;
        float ad   = fabsf(d);
        float c    = fminf(ad, 1.0f);
        float le   = c * (ad - 0.5f * c);
        outd[base + e] = diff;
        outm[base + e] = mk;
        accL += le * mk;
    }

    int gstart = half ? HALF0 : 0;
    int gend   = half ? NGRP : HALF0;
    for (int g = gstart + tid; g < gend; g += K2_THREADS) {
        int e0 = 3 + (g << 2);
        int i0 = e0 / LNUM;
        int j0 = e0 - i0 * LNUM;
        float dvv[4], mvv[4];
#pragma unroll
        for (int n = 0; n < 4; n++) {
            int jn = j0 + n;
            int wrap = (jn >= LNUM) ? 1 : 0;
            int in = i0 + wrap;
            jn -= LNUM * wrap;
            float2 mi2 = s_mm[in];
            float2 mj2 = s_mm[jn];
            float diff = mi2.x - mj2.x;
            float mk   = mi2.y * mj2.y;
            float d    = __ldg(relb + e0 + n) - diff;
            float ad   = fabsf(d);
            float c    = fminf(ad, 1.0f);
            float le   = c * (ad - 0.5f * c);
            dvv[n] = diff;
            mvv[n] = mk;
            accL += le * mk;
        }
        *reinterpret_cast<float4*>(outd + base + e0) =
            make_float4(dvv[0], dvv[1], dvv[2], dvv[3]);
        *reinterpret_cast<float4*>(outm + base + e0) =
            make_float4(mvv[0], mvv[1], mvv[2], mvv[3]);
    }

    double dL = (double)accL;
#pragma unroll
    for (int o = 16; o > 0; o >>= 1)
        dL += __shfl_down_sync(FULLM, dL, o);
    if (lane == 0) redL[wid] = dL;
    __syncthreads();
    if (tid == 0) {
        double tL = 0.0;
#pragma unroll
        for (int w = 0; w < K2_THREADS / 32; w++) tL += redL[w];
        g_partL[blk] = tL;                   // plain store, no atomics
    }
}

// ---- K3: final reduction -> loss scalar -----------------------------------
__global__ __launch_bounds__(512) void k3_final(float* __restrict__ out)
{
    __shared__ double rL[16], rM[16];
    int tid  = threadIdx.x;
    int wid  = tid >> 5;
    int lane = tid & 31;

    double L = 0.0, M = 0.0;
    for (int i = tid; i < K2_BLOCKS; i += 512) L += g_partL[i];
    for (int b = tid; b < BS; b += 512) {
        double c = (double)g_cnt[b];
        M += c * c;                          // sum_ij mi*mj == (sum m)^2
    }
#pragma unroll
    for (int o = 16; o > 0; o >>= 1) {
        L += __shfl_down_sync(FULLM, L, o);
        M += __shfl_down_sync(FULLM, M, o);
    }
    if (lane == 0) { rL[wid] = L; rM[wid] = M; }
    __syncthreads();
    if (wid == 0) {
        double vL = (lane < 16) ? rL[lane] : 0.0;
        double vM = (lane < 16) ? rM[lane] : 0.0;
#pragma unroll
        for (int o = 8; o > 0; o >>= 1) {
            vL += __shfl_down_sync(FULLM, vL, o);
            vM += __shfl_down_sync(FULLM, vM, o);
        }
        if (lane == 0) out[0] = (float)(vL / (vM + 1e-4));
    }
}

extern "C" void kernel_launch(void* const* d_in, const int* in_sizes, int n_in,
                              void* d_out, int out_size)
{
    const float* rel   = (const float*)d_in[0];   // [BS, L, L]
    const float* depth = (const float*)d_in[1];   // [BS, 1, IMG, IMG]
    const float* lm    = (const float*)d_in[2];   // [BS, L, 2]
    const float* sf    = (const float*)d_in[3];   // [BS, 2]
    const float* bbox  = (const float*)d_in[4];   // [BS, 4]
    float* out = (float*)d_out;                   // [loss | diff | mask]

    k1_medians<<<BS, 512>>>(depth, lm, sf, bbox);
    k2_pairwise<<<K2_BLOCKS, K2_THREADS>>>(rel, out);
    k3_final<<<1, 512>>>(out);
}